// round 1
// baseline (speedup 1.0000x reference)
#include <cuda_runtime.h>
#include <mma.h>
#include <math.h>

using namespace nvcuda;

#define BATCH 256
#define DIN   512
#define TSEQ  512
#define HID   1024
#define NG    4096      // 4 * HID, gate-interleaved
#define KTOT  1536      // HID + DIN
#define NCLS  1000

// ---------------- static device scratch (no allocations allowed) ----------------
__device__ float g_xT[(size_t)TSEQ * BATCH * DIN];   // 268 MB: x transposed to [T][B][D]
__device__ float g_W[(size_t)KTOT * NG];             // 25 MB:  [Wh; Wx] gate-interleaved
__device__ float g_bias[NG];
__device__ float g_h[2][(size_t)BATCH * HID];        // double-buffered hidden state
__device__ float g_c[(size_t)BATCH * HID];           // cell state

// ---------------- init: zero h[0] and c ----------------
__global__ void init_kernel() {
    size_t i = blockIdx.x * (size_t)blockDim.x + threadIdx.x;
    if (i < (size_t)BATCH * HID) {
        g_h[0][i] = 0.0f;
        g_c[i]    = 0.0f;
    }
}

// ---------------- pack weights: g_W[k][u*4+gate], gates ordered (g,f,i,o) ----------------
__global__ void pack_kernel(const float* __restrict__ Wfx, const float* __restrict__ Wfh,
                            const float* __restrict__ Wgx, const float* __restrict__ Wgh,
                            const float* __restrict__ Wix, const float* __restrict__ Wih,
                            const float* __restrict__ Wox, const float* __restrict__ Woh,
                            const float* __restrict__ bf,  const float* __restrict__ bg,
                            const float* __restrict__ bi,  const float* __restrict__ bo) {
    size_t idx = blockIdx.x * (size_t)blockDim.x + threadIdx.x;
    size_t total = (size_t)KTOT * NG;
    if (idx >= total) return;
    int e = (int)(idx % NG);
    int k = (int)(idx / NG);
    int u = e >> 2;
    int gate = e & 3;
    float v;
    if (k < HID) {
        const float* W = (gate == 0) ? Wgh : (gate == 1) ? Wfh : (gate == 2) ? Wih : Woh;
        v = W[(size_t)k * HID + u];
    } else {
        int d = k - HID;
        const float* W = (gate == 0) ? Wgx : (gate == 1) ? Wfx : (gate == 2) ? Wix : Wox;
        v = W[(size_t)d * HID + u];
    }
    g_W[idx] = v;
    if (idx < NG) {
        const float* b = (gate == 0) ? bg : (gate == 1) ? bf : (gate == 2) ? bi : bo;
        g_bias[e] = b[u];
    }
}

// ---------------- transpose x [B,D,T] -> xT [T][B*D] ----------------
// Treated as 2D transpose of [R=BATCH*DIN rows][TSEQ cols].
__global__ void transpose_kernel(const float* __restrict__ x) {
    __shared__ float tile[32][33];
    int t0 = blockIdx.x * 32;
    int r0 = blockIdx.y * 32;
    int tx = threadIdx.x;
    int ty = threadIdx.y;     // blockDim = (32, 8)
#pragma unroll
    for (int i = 0; i < 32; i += 8)
        tile[ty + i][tx] = x[(size_t)(r0 + ty + i) * TSEQ + (t0 + tx)];
    __syncthreads();
#pragma unroll
    for (int i = 0; i < 32; i += 8)
        g_xT[(size_t)(t0 + ty + i) * (BATCH * DIN) + (r0 + tx)] = tile[tx][ty + i];
}

// ---------------- per-timestep fused GEMM + LSTM cell update ----------------
// gates[b, e] = tanh( sum_k [h|x_t][b,k] * Wcat[k,e] + bias[e] ),  e = u*4 + (g,f,i,o)
// c = g*i + c*f ;  h_out = tanh(c)*o
#define MB  128
#define NB  64
#define KC  16
#define LDA 24
#define LDB 72
#define LDC 72

__global__ void __launch_bounds__(128) step_kernel(int t) {
    __shared__ float smem[MB * LDC];          // 9216 floats = 36 KB (staging overlaps front)
    float* sA = smem;                          // MB*LDA = 3072 floats
    float* sB = smem + MB * LDA;               // KC*LDB = 1152 floats

    const int tid  = threadIdx.x;
    const int warp = tid >> 5;
    const int b0   = blockIdx.y * MB;
    const int n0   = blockIdx.x * NB;

    const float* __restrict__ hin  = g_h[t & 1];
    float*       __restrict__ hout = g_h[(t + 1) & 1];

    wmma::fragment<wmma::accumulator, 16, 16, 8, float> acc[2][4];
#pragma unroll
    for (int am = 0; am < 2; ++am)
#pragma unroll
        for (int bn = 0; bn < 4; ++bn)
            wmma::fill_fragment(acc[am][bn], 0.0f);

    for (int kc = 0; kc < KTOT; kc += KC) {
        // stage A: [h | x_t] tile, MB rows x KC cols
#pragma unroll
        for (int j = 0; j < 16; ++j) {
            int e   = j * 128 + tid;
            int row = e >> 4;
            int col = e & 15;
            int k   = kc + col;
            float v;
            if (k < HID)
                v = hin[(size_t)(b0 + row) * HID + k];
            else
                v = g_xT[(size_t)t * (BATCH * DIN) + (size_t)(b0 + row) * DIN + (k - HID)];
            sA[row * LDA + col] = v;
        }
        // stage B: KC x NB of packed weights
#pragma unroll
        for (int j = 0; j < 8; ++j) {
            int e  = j * 128 + tid;
            int kr = e >> 6;
            int n  = e & 63;
            sB[kr * LDB + n] = g_W[(size_t)(kc + kr) * NG + (n0 + n)];
        }
        __syncthreads();

#pragma unroll
        for (int kk = 0; kk < KC; kk += 8) {
            wmma::fragment<wmma::matrix_a, 16, 16, 8, wmma::precision::tf32, wmma::row_major> af[2];
            wmma::fragment<wmma::matrix_b, 16, 16, 8, wmma::precision::tf32, wmma::row_major> bfr[4];
#pragma unroll
            for (int am = 0; am < 2; ++am) {
                wmma::load_matrix_sync(af[am], sA + (warp * 32 + am * 16) * LDA + kk, LDA);
#pragma unroll
                for (int i = 0; i < af[am].num_elements; ++i)
                    af[am].x[i] = wmma::__float_to_tf32(af[am].x[i]);
            }
#pragma unroll
            for (int bn = 0; bn < 4; ++bn) {
                wmma::load_matrix_sync(bfr[bn], sB + kk * LDB + bn * 16, LDB);
#pragma unroll
                for (int i = 0; i < bfr[bn].num_elements; ++i)
                    bfr[bn].x[i] = wmma::__float_to_tf32(bfr[bn].x[i]);
            }
#pragma unroll
            for (int am = 0; am < 2; ++am)
#pragma unroll
                for (int bn = 0; bn < 4; ++bn)
                    wmma::mma_sync(acc[am][bn], af[am], bfr[bn], acc[am][bn]);
        }
        __syncthreads();
    }

    // epilogue: dump C tile to smem, then fused gate math
#pragma unroll
    for (int am = 0; am < 2; ++am)
#pragma unroll
        for (int bn = 0; bn < 4; ++bn)
            wmma::store_matrix_sync(smem + (warp * 32 + am * 16) * LDC + bn * 16,
                                    acc[am][bn], LDC, wmma::mem_row_major);
    __syncthreads();

    const int u0 = n0 >> 2;   // 16 hidden units per block
#pragma unroll
    for (int p = 0; p < 16; ++p) {
        int e = p * 128 + tid;  // 0..2047  = r*16 + u
        int r = e >> 4;
        int u = e & 15;
        float gg = tanhf(smem[r * LDC + u * 4 + 0] + g_bias[n0 + u * 4 + 0]);
        float ff = tanhf(smem[r * LDC + u * 4 + 1] + g_bias[n0 + u * 4 + 1]);
        float ii = tanhf(smem[r * LDC + u * 4 + 2] + g_bias[n0 + u * 4 + 2]);
        float oo = tanhf(smem[r * LDC + u * 4 + 3] + g_bias[n0 + u * 4 + 3]);
        size_t cidx = (size_t)(b0 + r) * HID + (u0 + u);
        float c = gg * ii + g_c[cidx] * ff;
        g_c[cidx]  = c;
        hout[cidx] = tanhf(c) * oo;
    }
}

// ---------------- head: softmax(h @ W_ph + b_p) ----------------
__global__ void __launch_bounds__(256) head_kernel(const float* __restrict__ Wph,
                                                   const float* __restrict__ bp,
                                                   float* __restrict__ out) {
    __shared__ float hs[HID];
    __shared__ float lg[NCLS];
    __shared__ float red[256];
    int b   = blockIdx.x;
    int tid = threadIdx.x;
    const float* h = g_h[0];   // after 512 steps, final h lives in buffer 0

    for (int i = tid; i < HID; i += 256)
        hs[i] = h[(size_t)b * HID + i];
    __syncthreads();

    for (int c = tid; c < NCLS; c += 256) {
        float acc = bp[c];
#pragma unroll 8
        for (int k = 0; k < HID; ++k)
            acc += hs[k] * Wph[(size_t)k * NCLS + c];
        lg[c] = acc;
    }
    __syncthreads();

    float m = -1e30f;
    for (int c = tid; c < NCLS; c += 256) m = fmaxf(m, lg[c]);
    red[tid] = m;
    __syncthreads();
    for (int s = 128; s > 0; s >>= 1) {
        if (tid < s) red[tid] = fmaxf(red[tid], red[tid + s]);
        __syncthreads();
    }
    m = red[0];
    __syncthreads();

    float sum = 0.0f;
    for (int c = tid; c < NCLS; c += 256) {
        float ex = expf(lg[c] - m);
        lg[c] = ex;
        sum += ex;
    }
    red[tid] = sum;
    __syncthreads();
    for (int s = 128; s > 0; s >>= 1) {
        if (tid < s) red[tid] += red[tid + s];
        __syncthreads();
    }
    float inv = 1.0f / red[0];
    for (int c = tid; c < NCLS; c += 256)
        out[(size_t)b * NCLS + c] = lg[c] * inv;
}

// ---------------- launch ----------------
extern "C" void kernel_launch(void* const* d_in, const int* in_sizes, int n_in,
                              void* d_out, int out_size) {
    (void)in_sizes; (void)n_in; (void)out_size;
    const float* x   = (const float*)d_in[0];
    const float* Wfx = (const float*)d_in[1];
    const float* Wfh = (const float*)d_in[2];
    const float* Wgx = (const float*)d_in[3];
    const float* Wgh = (const float*)d_in[4];
    const float* Wix = (const float*)d_in[5];
    const float* Wih = (const float*)d_in[6];
    const float* Wox = (const float*)d_in[7];
    const float* Woh = (const float*)d_in[8];
    const float* Wph = (const float*)d_in[9];
    const float* bf  = (const float*)d_in[10];
    const float* bg  = (const float*)d_in[11];
    const float* bi  = (const float*)d_in[12];
    const float* bo  = (const float*)d_in[13];
    const float* bp  = (const float*)d_in[14];
    float* out = (float*)d_out;

    init_kernel<<<(BATCH * HID + 255) / 256, 256>>>();

    size_t packN = (size_t)KTOT * NG;
    pack_kernel<<<(unsigned)((packN + 255) / 256), 256>>>(Wfx, Wfh, Wgx, Wgh,
                                                          Wix, Wih, Wox, Woh,
                                                          bf, bg, bi, bo);

    transpose_kernel<<<dim3(TSEQ / 32, (BATCH * DIN) / 32), dim3(32, 8)>>>(x);

    for (int t = 0; t < TSEQ; ++t)
        step_kernel<<<dim3(NG / NB, BATCH / MB), 128>>>(t);

    head_kernel<<<BATCH, 256>>>(Wph, bp, out);
}

// round 3
// speedup vs baseline: 1.4575x; 1.4575x over previous
#include <cuda_runtime.h>
#include <mma.h>
#include <math.h>
#include <cstdint>

using namespace nvcuda;

#define BATCH 256
#define DIN   512
#define TSEQ  512
#define HID   1024
#define NG    4096      // 4 * HID, gate-interleaved
#define KTOT  1536      // HID + DIN
#define NCLS  1000

// ---------------- static device scratch (no allocations allowed) ----------------
__device__ float g_xT[(size_t)TSEQ * BATCH * DIN];   // 268 MB: x transposed to [T][B][D]
__device__ float g_W[(size_t)KTOT * NG];             // 25 MB:  [Wh; Wx] gate-interleaved
__device__ float g_bias[NG];
__device__ float g_h[2][(size_t)BATCH * HID];        // double-buffered hidden state
__device__ float g_c[(size_t)BATCH * HID];           // cell state

// ---------------- init: zero h[0] and c ----------------
__global__ void init_kernel() {
    size_t i = blockIdx.x * (size_t)blockDim.x + threadIdx.x;
    if (i < (size_t)BATCH * HID) {
        g_h[0][i] = 0.0f;
        g_c[i]    = 0.0f;
    }
}

// ---------------- pack weights: g_W[k][u*4+gate], gates ordered (g,f,i,o) ----------------
__global__ void pack_kernel(const float* __restrict__ Wfx, const float* __restrict__ Wfh,
                            const float* __restrict__ Wgx, const float* __restrict__ Wgh,
                            const float* __restrict__ Wix, const float* __restrict__ Wih,
                            const float* __restrict__ Wox, const float* __restrict__ Woh,
                            const float* __restrict__ bf,  const float* __restrict__ bg,
                            const float* __restrict__ bi,  const float* __restrict__ bo) {
    size_t idx = blockIdx.x * (size_t)blockDim.x + threadIdx.x;
    size_t total = (size_t)KTOT * NG;
    if (idx >= total) return;
    int e = (int)(idx % NG);
    int k = (int)(idx / NG);
    int u = e >> 2;
    int gate = e & 3;
    float v;
    if (k < HID) {
        const float* W = (gate == 0) ? Wgh : (gate == 1) ? Wfh : (gate == 2) ? Wih : Woh;
        v = W[(size_t)k * HID + u];
    } else {
        int d = k - HID;
        const float* W = (gate == 0) ? Wgx : (gate == 1) ? Wfx : (gate == 2) ? Wix : Wox;
        v = W[(size_t)d * HID + u];
    }
    g_W[idx] = v;
    if (idx < NG) {
        const float* b = (gate == 0) ? bg : (gate == 1) ? bf : (gate == 2) ? bi : bo;
        g_bias[e] = b[u];
    }
}

// ---------------- transpose x [B,D,T] -> xT [T][B*D] ----------------
__global__ void transpose_kernel(const float* __restrict__ x) {
    __shared__ float tile[32][33];
    int t0 = blockIdx.x * 32;
    int r0 = blockIdx.y * 32;
    int tx = threadIdx.x;
    int ty = threadIdx.y;     // blockDim = (32, 8)
#pragma unroll
    for (int i = 0; i < 32; i += 8)
        tile[ty + i][tx] = x[(size_t)(r0 + ty + i) * TSEQ + (t0 + tx)];
    __syncthreads();
#pragma unroll
    for (int i = 0; i < 32; i += 8)
        g_xT[(size_t)(t0 + ty + i) * (BATCH * DIN) + (r0 + tx)] = tile[tx][ty + i];
}

// ================= per-timestep fused GEMM + LSTM cell update =================
// Block tile: 128 rows (batch) x 64 cols (gate units). 256 threads = 8 warps,
// warp tile 32x32 (2x2 of m16n16k8 tf32). 3-stage cp.async pipeline, KC=16.
#define MB   128
#define NB   64
#define KC   16
#define LDA  20          // 16 + 4 pad
#define LDB  68          // 64 + 4 pad
#define LDCC 68
#define STAGES 3
#define ASTG (MB * LDA)  // 2560 floats per A stage
#define BSTG (KC * LDB)  // 1088 floats per B stage
#define NKIT (KTOT / KC) // 96

__device__ __forceinline__ void cp16(uint32_t dst_smem, const float* src) {
    asm volatile("cp.async.cg.shared.global [%0], [%1], 16;\n"
                 :: "r"(dst_smem), "l"(src));
}
__device__ __forceinline__ void cp_commit() {
    asm volatile("cp.async.commit_group;\n");
}
template <int N>
__device__ __forceinline__ void cp_wait() {
    asm volatile("cp.async.wait_group %0;\n" :: "n"(N));
}

__global__ void __launch_bounds__(256) step_kernel(int t) {
    __shared__ float smem[STAGES * (ASTG + BSTG)];   // 43,776 B; reused as C in epilogue
    float* sA = smem;                    // [STAGES][ASTG]
    float* sB = smem + STAGES * ASTG;    // [STAGES][BSTG]

    const int tid  = threadIdx.x;
    const int warp = tid >> 5;
    const int wm   = warp >> 1;          // 0..3  (m offset wm*32)
    const int wn   = warp & 1;           // 0..1  (n offset wn*32)
    const int b0   = blockIdx.y * MB;
    const int n0   = blockIdx.x * NB;

    const float* __restrict__ hin  = g_h[t & 1];
    float*       __restrict__ hout = g_h[(t + 1) & 1];
    const float* __restrict__ xTt  = g_xT + (size_t)t * (BATCH * DIN);

    uint32_t smem_base;
    {
        void* p = (void*)smem;
        asm("{ .reg .u64 tt; cvta.to.shared.u64 tt, %1; cvt.u32.u64 %0, tt; }"
            : "=r"(smem_base) : "l"(p));
    }

    // precompute per-thread staging indices
    const int arow0 = (tid * 2) >> 2;          // A: 2 float4 per thread
    const int aq0   = (tid * 2) & 3;
    const int arow1 = (tid * 2 + 1) >> 2;
    const int aq1   = (tid * 2 + 1) & 3;
    const int brow  = tid >> 4;                // B: 1 float4 per thread
    const int bq    = tid & 15;

    auto stage = [&](int s, int kc) {
        // A tile: rows b0..b0+127, cols kc..kc+15 of [h | x]
        const float* srcbase;
        int rstride;
        if (kc < HID) { srcbase = hin + (size_t)b0 * HID + kc;        rstride = HID; }
        else          { srcbase = xTt + (size_t)b0 * DIN + (kc - HID); rstride = DIN; }
        uint32_t adst = smem_base + (uint32_t)(s * ASTG) * 4u;
        cp16(adst + (uint32_t)(arow0 * LDA + aq0 * 4) * 4u, srcbase + (size_t)arow0 * rstride + aq0 * 4);
        cp16(adst + (uint32_t)(arow1 * LDA + aq1 * 4) * 4u, srcbase + (size_t)arow1 * rstride + aq1 * 4);
        // B tile: KC x 64 of packed weights
        uint32_t bdst = smem_base + (uint32_t)(STAGES * ASTG + s * BSTG) * 4u;
        cp16(bdst + (uint32_t)(brow * LDB + bq * 4) * 4u,
             g_W + (size_t)(kc + brow) * NG + n0 + bq * 4);
        cp_commit();
    };

    wmma::fragment<wmma::accumulator, 16, 16, 8, float> acc[2][2];
#pragma unroll
    for (int am = 0; am < 2; ++am)
#pragma unroll
        for (int bn = 0; bn < 2; ++bn)
            wmma::fill_fragment(acc[am][bn], 0.0f);

    stage(0, 0);
    stage(1, KC);

    for (int it = 0; it < NKIT; ++it) {
        cp_wait<1>();
        __syncthreads();

        const int s = it % STAGES;
        const float* cA = sA + s * ASTG;
        const float* cB = sB + s * BSTG;

#pragma unroll
        for (int kk = 0; kk < KC; kk += 8) {
            wmma::fragment<wmma::matrix_a, 16, 16, 8, wmma::precision::tf32, wmma::row_major> af[2];
            wmma::fragment<wmma::matrix_b, 16, 16, 8, wmma::precision::tf32, wmma::row_major> bfr[2];
#pragma unroll
            for (int am = 0; am < 2; ++am) {
                wmma::load_matrix_sync(af[am], cA + (wm * 32 + am * 16) * LDA + kk, LDA);
#pragma unroll
                for (int i = 0; i < af[am].num_elements; ++i)
                    af[am].x[i] = wmma::__float_to_tf32(af[am].x[i]);
            }
#pragma unroll
            for (int bn = 0; bn < 2; ++bn) {
                wmma::load_matrix_sync(bfr[bn], cB + kk * LDB + wn * 32 + bn * 16, LDB);
#pragma unroll
                for (int i = 0; i < bfr[bn].num_elements; ++i)
                    bfr[bn].x[i] = wmma::__float_to_tf32(bfr[bn].x[i]);
            }
#pragma unroll
            for (int am = 0; am < 2; ++am)
#pragma unroll
                for (int bn = 0; bn < 2; ++bn)
                    wmma::mma_sync(acc[am][bn], af[am], bfr[bn], acc[am][bn]);
        }

        // prefetch stage it+2 (always commit to keep group count consistent)
        if (it + 2 < NKIT) stage((it + 2) % STAGES, (it + 2) * KC);
        else               cp_commit();
    }

    // ---------------- epilogue: C -> gates -> cell update ----------------
    cp_wait<0>();
    __syncthreads();
    float* C = smem;    // 128 x LDCC floats = 34,816 B (fits in pipeline smem)
#pragma unroll
    for (int am = 0; am < 2; ++am)
#pragma unroll
        for (int bn = 0; bn < 2; ++bn)
            wmma::store_matrix_sync(C + (wm * 32 + am * 16) * LDCC + wn * 32 + bn * 16,
                                    acc[am][bn], LDCC, wmma::mem_row_major);
    __syncthreads();

    const int u0 = n0 >> 2;   // 16 hidden units per block
#pragma unroll
    for (int p = 0; p < 8; ++p) {
        int e = p * 256 + tid;  // 0..2047 = r*16 + u
        int r = e >> 4;
        int u = e & 15;
        float gg = tanhf(C[r * LDCC + u * 4 + 0] + g_bias[n0 + u * 4 + 0]);
        float ff = tanhf(C[r * LDCC + u * 4 + 1] + g_bias[n0 + u * 4 + 1]);
        float ii = tanhf(C[r * LDCC + u * 4 + 2] + g_bias[n0 + u * 4 + 2]);
        float oo = tanhf(C[r * LDCC + u * 4 + 3] + g_bias[n0 + u * 4 + 3]);
        size_t cidx = (size_t)(b0 + r) * HID + (u0 + u);
        float c = gg * ii + g_c[cidx] * ff;
        g_c[cidx]  = c;
        hout[cidx] = tanhf(c) * oo;
    }
}

// ---------------- head: softmax(h @ W_ph + b_p) ----------------
__global__ void __launch_bounds__(256) head_kernel(const float* __restrict__ Wph,
                                                   const float* __restrict__ bp,
                                                   float* __restrict__ out) {
    __shared__ float hs[HID];
    __shared__ float lg[NCLS];
    __shared__ float red[256];
    int b   = blockIdx.x;
    int tid = threadIdx.x;
    const float* h = g_h[0];   // after 512 steps, final h lives in buffer 0

    for (int i = tid; i < HID; i += 256)
        hs[i] = h[(size_t)b * HID + i];
    __syncthreads();

    for (int c = tid; c < NCLS; c += 256) {
        float acc = bp[c];
#pragma unroll 8
        for (int k = 0; k < HID; ++k)
            acc += hs[k] * Wph[(size_t)k * NCLS + c];
        lg[c] = acc;
    }
    __syncthreads();

    float m = -1e30f;
    for (int c = tid; c < NCLS; c += 256) m = fmaxf(m, lg[c]);
    red[tid] = m;
    __syncthreads();
    for (int s = 128; s > 0; s >>= 1) {
        if (tid < s) red[tid] = fmaxf(red[tid], red[tid + s]);
        __syncthreads();
    }
    m = red[0];
    __syncthreads();

    float sum = 0.0f;
    for (int c = tid; c < NCLS; c += 256) {
        float ex = expf(lg[c] - m);
        lg[c] = ex;
        sum += ex;
    }
    red[tid] = sum;
    __syncthreads();
    for (int s = 128; s > 0; s >>= 1) {
        if (tid < s) red[tid] += red[tid + s];
        __syncthreads();
    }
    float inv = 1.0f / red[0];
    for (int c = tid; c < NCLS; c += 256)
        out[(size_t)b * NCLS + c] = lg[c] * inv;
}

// ---------------- launch ----------------
extern "C" void kernel_launch(void* const* d_in, const int* in_sizes, int n_in,
                              void* d_out, int out_size) {
    (void)in_sizes; (void)n_in; (void)out_size;
    const float* x   = (const float*)d_in[0];
    const float* Wfx = (const float*)d_in[1];
    const float* Wfh = (const float*)d_in[2];
    const float* Wgx = (const float*)d_in[3];
    const float* Wgh = (const float*)d_in[4];
    const float* Wix = (const float*)d_in[5];
    const float* Wih = (const float*)d_in[6];
    const float* Wox = (const float*)d_in[7];
    const float* Woh = (const float*)d_in[8];
    const float* Wph = (const float*)d_in[9];
    const float* bf  = (const float*)d_in[10];
    const float* bg  = (const float*)d_in[11];
    const float* bi  = (const float*)d_in[12];
    const float* bo  = (const float*)d_in[13];
    const float* bp  = (const float*)d_in[14];
    float* out = (float*)d_out;

    init_kernel<<<(BATCH * HID + 255) / 256, 256>>>();

    size_t packN = (size_t)KTOT * NG;
    pack_kernel<<<(unsigned)((packN + 255) / 256), 256>>>(Wfx, Wfh, Wgx, Wgh,
                                                          Wix, Wih, Wox, Woh,
                                                          bf, bg, bi, bo);

    transpose_kernel<<<dim3(TSEQ / 32, (BATCH * DIN) / 32), dim3(32, 8)>>>(x);

    for (int t = 0; t < TSEQ; ++t)
        step_kernel<<<dim3(NG / NB, BATCH / MB), 256>>>(t);

    head_kernel<<<BATCH, 256>>>(Wph, bp, out);
}

// round 4
// speedup vs baseline: 1.7991x; 1.2343x over previous
#include <cuda_runtime.h>
#include <mma.h>
#include <math.h>
#include <cstdint>

using namespace nvcuda;

#define BATCH 256
#define DIN   512
#define TSEQ  512
#define HID   1024
#define NG    4096      // 4 * HID, gate-interleaved
#define KTOT  1536      // HID + DIN
#define NCLS  1000

// ---------------- static device scratch (no allocations allowed) ----------------
__device__ float g_xT[(size_t)TSEQ * BATCH * DIN];   // 268 MB: x transposed to [T][B][D], tf32-rounded
__device__ float g_W[(size_t)KTOT * NG];             // 25 MB:  [Wh; Wx] gate-interleaved, tf32-rounded
__device__ float g_bias[NG];
__device__ float g_h[2][(size_t)BATCH * HID];        // double-buffered hidden state (tf32-rounded)
__device__ float g_c[(size_t)BATCH * HID];           // cell state (full fp32)

// round-to-nearest tf32 (identical numerics to converting at mma-load time)
__device__ __forceinline__ float rtf32(float v) {
    uint32_t u;
    asm("cvt.rna.tf32.f32 %0, %1;" : "=r"(u) : "f"(v));
    return __uint_as_float(u);
}

// ---------------- init: zero h[0] and c ----------------
__global__ void init_kernel() {
    size_t i = blockIdx.x * (size_t)blockDim.x + threadIdx.x;
    if (i < (size_t)BATCH * HID) {
        g_h[0][i] = 0.0f;
        g_c[i]    = 0.0f;
    }
}

// ---------------- pack weights: g_W[k][u*4+gate], gates ordered (g,f,i,o) ----------------
__global__ void pack_kernel(const float* __restrict__ Wfx, const float* __restrict__ Wfh,
                            const float* __restrict__ Wgx, const float* __restrict__ Wgh,
                            const float* __restrict__ Wix, const float* __restrict__ Wih,
                            const float* __restrict__ Wox, const float* __restrict__ Woh,
                            const float* __restrict__ bf,  const float* __restrict__ bg,
                            const float* __restrict__ bi,  const float* __restrict__ bo) {
    size_t idx = blockIdx.x * (size_t)blockDim.x + threadIdx.x;
    size_t total = (size_t)KTOT * NG;
    if (idx >= total) return;
    int e = (int)(idx % NG);
    int k = (int)(idx / NG);
    int u = e >> 2;
    int gate = e & 3;
    float v;
    if (k < HID) {
        const float* W = (gate == 0) ? Wgh : (gate == 1) ? Wfh : (gate == 2) ? Wih : Woh;
        v = W[(size_t)k * HID + u];
    } else {
        int d = k - HID;
        const float* W = (gate == 0) ? Wgx : (gate == 1) ? Wfx : (gate == 2) ? Wix : Wox;
        v = W[(size_t)d * HID + u];
    }
    g_W[idx] = rtf32(v);
    if (idx < NG) {
        const float* b = (gate == 0) ? bg : (gate == 1) ? bf : (gate == 2) ? bi : bo;
        g_bias[e] = b[u];
    }
}

// ---------------- transpose x [B,D,T] -> xT [T][B*D], tf32-rounded ----------------
__global__ void transpose_kernel(const float* __restrict__ x) {
    __shared__ float tile[32][33];
    int t0 = blockIdx.x * 32;
    int r0 = blockIdx.y * 32;
    int tx = threadIdx.x;
    int ty = threadIdx.y;     // blockDim = (32, 8)
#pragma unroll
    for (int i = 0; i < 32; i += 8)
        tile[ty + i][tx] = x[(size_t)(r0 + ty + i) * TSEQ + (t0 + tx)];
    __syncthreads();
#pragma unroll
    for (int i = 0; i < 32; i += 8)
        g_xT[(size_t)(t0 + ty + i) * (BATCH * DIN) + (r0 + tx)] = rtf32(tile[tx][ty + i]);
}

// ================= per-timestep fused GEMM + LSTM cell update =================
// Block tile: 64 rows (batch) x 64 cols (gate units). 128 threads = 4 warps,
// warp tile 32x32 (2x2 of m16n16k8 tf32). 3-stage cp.async pipeline, KC=32.
// grid = (NG/NB=64, BATCH/MB=4) = 256 blocks -> ~2 co-resident blocks per SM.
#define MB   64
#define NB   64
#define KC   32
#define LDA  36          // 32 + 4 pad
#define LDB  68          // 64 + 4 pad
#define LDCC 68
#define STAGES 3
#define ASTG (MB * LDA)  // 2304 floats per A stage
#define BSTG (KC * LDB)  // 2176 floats per B stage
#define NKIT (KTOT / KC) // 48

__device__ __forceinline__ void cp16(uint32_t dst_smem, const float* src) {
    asm volatile("cp.async.cg.shared.global [%0], [%1], 16;\n"
                 :: "r"(dst_smem), "l"(src));
}
__device__ __forceinline__ void cp_commit() {
    asm volatile("cp.async.commit_group;\n");
}
template <int N>
__device__ __forceinline__ void cp_wait() {
    asm volatile("cp.async.wait_group %0;\n" :: "n"(N));
}

__global__ void __launch_bounds__(128) step_kernel(int t) {
    __shared__ float smem[STAGES * (ASTG + BSTG)];   // 53,760 B; reused as C in epilogue
    float* sA = smem;                    // [STAGES][ASTG]
    float* sB = smem + STAGES * ASTG;    // [STAGES][BSTG]

    const int tid  = threadIdx.x;
    const int warp = tid >> 5;
    const int wm   = warp >> 1;          // 0..1  (m offset wm*32)
    const int wn   = warp & 1;           // 0..1  (n offset wn*32)
    const int b0   = blockIdx.y * MB;
    const int n0   = blockIdx.x * NB;

    const float* __restrict__ hin  = g_h[t & 1];
    float*       __restrict__ hout = g_h[(t + 1) & 1];
    const float* __restrict__ xTt  = g_xT + (size_t)t * (BATCH * DIN);

    uint32_t smem_base;
    {
        void* p = (void*)smem;
        asm("{ .reg .u64 tt; cvta.to.shared.u64 tt, %1; cvt.u32.u64 %0, tt; }"
            : "=r"(smem_base) : "l"(p));
    }

    auto stage = [&](int s, int kc) {
        // A tile: rows b0..b0+63, cols kc..kc+31 of [h | x]  (kc chunks never straddle HID)
        const float* srcbase;
        int rstride;
        if (kc < HID) { srcbase = hin + (size_t)b0 * HID + kc;         rstride = HID; }
        else          { srcbase = xTt + (size_t)b0 * DIN + (kc - HID); rstride = DIN; }
        uint32_t adst = smem_base + (uint32_t)(s * ASTG) * 4u;
#pragma unroll
        for (int j = 0; j < 4; ++j) {
            int idx = j * 128 + tid;       // 512 float4 total
            int row = idx >> 3;            // 8 float4 per row
            int q   = idx & 7;
            cp16(adst + (uint32_t)(row * LDA + q * 4) * 4u,
                 srcbase + (size_t)row * rstride + q * 4);
        }
        // B tile: KC x 64 of packed weights
        uint32_t bdst = smem_base + (uint32_t)(STAGES * ASTG + s * BSTG) * 4u;
#pragma unroll
        for (int j = 0; j < 4; ++j) {
            int idx = j * 128 + tid;       // 512 float4 total
            int row = idx >> 4;            // 16 float4 per row
            int q   = idx & 15;
            cp16(bdst + (uint32_t)(row * LDB + q * 4) * 4u,
                 g_W + (size_t)(kc + row) * NG + n0 + q * 4);
        }
        cp_commit();
    };

    wmma::fragment<wmma::accumulator, 16, 16, 8, float> acc[2][2];
#pragma unroll
    for (int am = 0; am < 2; ++am)
#pragma unroll
        for (int bn = 0; bn < 2; ++bn)
            wmma::fill_fragment(acc[am][bn], 0.0f);

    stage(0, 0);
    stage(1, KC);

    for (int it = 0; it < NKIT; ++it) {
        cp_wait<1>();
        __syncthreads();

        const int s = it % STAGES;
        const float* cA = sA + s * ASTG;
        const float* cB = sB + s * BSTG;

#pragma unroll
        for (int kk = 0; kk < KC; kk += 8) {
            wmma::fragment<wmma::matrix_a, 16, 16, 8, wmma::precision::tf32, wmma::row_major> af[2];
            wmma::fragment<wmma::matrix_b, 16, 16, 8, wmma::precision::tf32, wmma::row_major> bfr[2];
#pragma unroll
            for (int am = 0; am < 2; ++am)
                wmma::load_matrix_sync(af[am], cA + (wm * 32 + am * 16) * LDA + kk, LDA);
#pragma unroll
            for (int bn = 0; bn < 2; ++bn)
                wmma::load_matrix_sync(bfr[bn], cB + kk * LDB + wn * 32 + bn * 16, LDB);
            // operands pre-rounded to tf32 in gmem — no conversion needed here
#pragma unroll
            for (int am = 0; am < 2; ++am)
#pragma unroll
                for (int bn = 0; bn < 2; ++bn)
                    wmma::mma_sync(acc[am][bn], af[am], bfr[bn], acc[am][bn]);
        }

        // prefetch stage it+2 (always commit to keep group count consistent)
        if (it + 2 < NKIT) stage((it + 2) % STAGES, (it + 2) * KC);
        else               cp_commit();
    }

    // ---------------- epilogue: C -> gates -> cell update ----------------
    cp_wait<0>();
    __syncthreads();
    float* C = smem;    // 64 x LDCC floats = 17,408 B (fits in pipeline smem)
#pragma unroll
    for (int am = 0; am < 2; ++am)
#pragma unroll
        for (int bn = 0; bn < 2; ++bn)
            wmma::store_matrix_sync(C + (wm * 32 + am * 16) * LDCC + wn * 32 + bn * 16,
                                    acc[am][bn], LDCC, wmma::mem_row_major);
    __syncthreads();

    const int u0 = n0 >> 2;   // 16 hidden units per block
#pragma unroll
    for (int p = 0; p < 8; ++p) {
        int e = p * 128 + tid;  // 0..1023 = r*16 + u
        int r = e >> 4;
        int u = e & 15;
        float gg = tanhf(C[r * LDCC + u * 4 + 0] + g_bias[n0 + u * 4 + 0]);
        float ff = tanhf(C[r * LDCC + u * 4 + 1] + g_bias[n0 + u * 4 + 1]);
        float ii = tanhf(C[r * LDCC + u * 4 + 2] + g_bias[n0 + u * 4 + 2]);
        float oo = tanhf(C[r * LDCC + u * 4 + 3] + g_bias[n0 + u * 4 + 3]);
        size_t cidx = (size_t)(b0 + r) * HID + (u0 + u);
        float c = gg * ii + g_c[cidx] * ff;
        g_c[cidx]  = c;
        hout[cidx] = rtf32(tanhf(c) * oo);
    }
}

// ---------------- head: softmax(h @ W_ph + b_p) ----------------
__global__ void __launch_bounds__(256) head_kernel(const float* __restrict__ Wph,
                                                   const float* __restrict__ bp,
                                                   float* __restrict__ out) {
    __shared__ float hs[HID];
    __shared__ float lg[NCLS];
    __shared__ float red[256];
    int b   = blockIdx.x;
    int tid = threadIdx.x;
    const float* h = g_h[0];   // after 512 steps, final h lives in buffer 0

    for (int i = tid; i < HID; i += 256)
        hs[i] = h[(size_t)b * HID + i];
    __syncthreads();

    for (int c = tid; c < NCLS; c += 256) {
        float acc = bp[c];
#pragma unroll 8
        for (int k = 0; k < HID; ++k)
            acc += hs[k] * Wph[(size_t)k * NCLS + c];
        lg[c] = acc;
    }
    __syncthreads();

    float m = -1e30f;
    for (int c = tid; c < NCLS; c += 256) m = fmaxf(m, lg[c]);
    red[tid] = m;
    __syncthreads();
    for (int s = 128; s > 0; s >>= 1) {
        if (tid < s) red[tid] = fmaxf(red[tid], red[tid + s]);
        __syncthreads();
    }
    m = red[0];
    __syncthreads();

    float sum = 0.0f;
    for (int c = tid; c < NCLS; c += 256) {
        float ex = expf(lg[c] - m);
        lg[c] = ex;
        sum += ex;
    }
    red[tid] = sum;
    __syncthreads();
    for (int s = 128; s > 0; s >>= 1) {
        if (tid < s) red[tid] += red[tid + s];
        __syncthreads();
    }
    float inv = 1.0f / red[0];
    for (int c = tid; c < NCLS; c += 256)
        out[(size_t)b * NCLS + c] = lg[c] * inv;
}

// ---------------- launch ----------------
extern "C" void kernel_launch(void* const* d_in, const int* in_sizes, int n_in,
                              void* d_out, int out_size) {
    (void)in_sizes; (void)n_in; (void)out_size;
    const float* x   = (const float*)d_in[0];
    const float* Wfx = (const float*)d_in[1];
    const float* Wfh = (const float*)d_in[2];
    const float* Wgx = (const float*)d_in[3];
    const float* Wgh = (const float*)d_in[4];
    const float* Wix = (const float*)d_in[5];
    const float* Wih = (const float*)d_in[6];
    const float* Wox = (const float*)d_in[7];
    const float* Woh = (const float*)d_in[8];
    const float* Wph = (const float*)d_in[9];
    const float* bf  = (const float*)d_in[10];
    const float* bg  = (const float*)d_in[11];
    const float* bi  = (const float*)d_in[12];
    const float* bo  = (const float*)d_in[13];
    const float* bp  = (const float*)d_in[14];
    float* out = (float*)d_out;

    init_kernel<<<(BATCH * HID + 255) / 256, 256>>>();

    size_t packN = (size_t)KTOT * NG;
    pack_kernel<<<(unsigned)((packN + 255) / 256), 256>>>(Wfx, Wfh, Wgx, Wgh,
                                                          Wix, Wih, Wox, Woh,
                                                          bf, bg, bi, bo);

    transpose_kernel<<<dim3(TSEQ / 32, (BATCH * DIN) / 32), dim3(32, 8)>>>(x);

    for (int t = 0; t < TSEQ; ++t)
        step_kernel<<<dim3(NG / NB, BATCH / MB), 128>>>(t);

    head_kernel<<<BATCH, 256>>>(Wph, bp, out);
}